// round 6
// baseline (speedup 1.0000x reference)
#include <cuda_runtime.h>

// DenseWarpLayer: bilinear warp, N=8, H=512, W=512, C=32 fp32.
// R6: 2D-tiled blocks for vertical L1 reuse. Each 256-thread block owns a
// 32-wide x 8-tall pixel tile and walks it row by row; the bottom-corner
// gather lines of row r are the top-corner lines of row r+1 and are still
// resident in L1 (~40cyc) instead of L2 (~250-500cyc). Mapping within a row
// is unchanged from R4/R5: 8 threads/pixel, every warp-level LDG.128/STG.128
// covers 4 full 128B lines. Flow is prefetched one row ahead. 32 regs /
// 8 blocks / 64 warps per SM preserved.

#define N_ 8
#define H_ 512
#define W_ 512
#define C4_ 8u            // 32 channels = 8 float4
#define ROW4 (W_ * C4_)   // float4 per image row = 4096
#define TILE_W 32u
#define TILE_H 8u
#define TILES_X (W_ / TILE_W)          // 16
#define TILES_Y (H_ / TILE_H)          // 64
#define TILES_PER_IMG (TILES_X * TILES_Y)  // 1024

__device__ __forceinline__ float4 bilerp4(const float4 tl, const float4 tr,
                                          const float4 bl, const float4 br,
                                          const float ax, const float ay)
{
    float4 r; float top, bot;
    top = tl.x + ax * (tr.x - tl.x); bot = bl.x + ax * (br.x - bl.x);
    r.x = top + ay * (bot - top);
    top = tl.y + ax * (tr.y - tl.y); bot = bl.y + ax * (br.y - bl.y);
    r.y = top + ay * (bot - top);
    top = tl.z + ax * (tr.z - tl.z); bot = bl.z + ax * (br.z - bl.z);
    r.z = top + ay * (bot - top);
    top = tl.w + ax * (tr.w - tl.w); bot = bl.w + ax * (br.w - bl.w);
    r.w = top + ay * (bot - top);
    return r;
}

__global__ __launch_bounds__(256, 8)
void dense_warp_kernel(const float* __restrict__ image,
                       const float* __restrict__ flow,
                       float* __restrict__ out)
{
    const unsigned tid  = threadIdx.x;
    const unsigned c4   = tid & 7u;        // channel quad
    const unsigned col  = tid >> 3;        // column within tile, 0..31
                                           // warp = 4 adjacent cols x 8 quads

    const unsigned blk  = blockIdx.x;
    const unsigned n    = blk >> 10;                 // / TILES_PER_IMG
    const unsigned rem  = blk & (TILES_PER_IMG - 1);
    const unsigned ty   = rem >> 4;                  // / TILES_X
    const unsigned tx   = rem & (TILES_X - 1);

    const unsigned x    = tx * TILE_W + col;         // pixel x (const per thread)
    const unsigned y0   = ty * TILE_H;               // first row of tile
    const unsigned nH   = n * H_;

    const float2* fl2  = reinterpret_cast<const float2*>(flow);
    const float4* img4 = reinterpret_cast<const float4*>(image);
    float4*       out4 = reinterpret_cast<float4*>(out);

    const unsigned imgBase = nH * (unsigned)W_;      // pixel index of (n,0,0)

    // prefetch flow for row 0
    float2 fln = __ldg(fl2 + (imgBase + y0 * W_ + x));

    #pragma unroll 1
    for (unsigned r = 0; r < TILE_H; ++r) {
        const unsigned y   = y0 + r;
        const unsigned pix = imgBase + y * W_ + x;

        const float2 fl = fln;
        if (r + 1u < TILE_H)
            fln = __ldg(fl2 + (pix + W_));           // prefetch next row's flow

        // query point, clamped floor, clamped alphas (faithful to reference)
        const float qy = (float)y - fl.x;
        const float qx = (float)x - fl.y;

        float fyf = floorf(qy);
        float fxf = floorf(qx);
        fyf = fminf(fmaxf(fyf, 0.0f), (float)(H_ - 2));
        fxf = fminf(fmaxf(fxf, 0.0f), (float)(W_ - 2));

        const float ay = fminf(fmaxf(qy - fyf, 0.0f), 1.0f);
        const float ax = fminf(fmaxf(qx - fxf, 0.0f), 1.0f);

        const unsigned rb =
            ((nH + (unsigned)(int)fyf) * W_ + (unsigned)(int)fxf) * C4_ + c4;

        const float4 tl = __ldg(img4 + rb);
        const float4 tr = __ldg(img4 + rb + C4_);
        const float4 bl = __ldg(img4 + rb + ROW4);
        const float4 br = __ldg(img4 + rb + ROW4 + C4_);

        out4[pix * C4_ + c4] = bilerp4(tl, tr, bl, br, ax, ay);
    }
}

extern "C" void kernel_launch(void* const* d_in, const int* in_sizes, int n_in,
                              void* d_out, int out_size)
{
    const float* image = (const float*)d_in[0];
    const float* flow  = (const float*)d_in[1];
    float* out = (float*)d_out;

    // N * TILES_PER_IMG = 8 * 1024 = 8192 blocks, 256 threads each
    dense_warp_kernel<<<8192, 256>>>(image, flow, out);
}